// round 15
// baseline (speedup 1.0000x reference)
#include <cuda_runtime.h>
#include <cuda_fp16.h>
#include <math.h>
#include <stdint.h>

#define NN 100000
#define EE 500000

__device__ float g_cnt[NN];
__device__ float g_sum1[(size_t)NN * 128];
__device__ float g_sum2[(size_t)NN * 128];
__device__ float g_proj[(size_t)NN * 128];
__device__ __half g_srcF[(size_t)EE * 128];
__device__ __half g_dstF[(size_t)EE * 128];
__device__ uint32_t g_WT1[128 * 96];
__device__ uint32_t g_WT2[128 * 96];

__device__ __forceinline__ float4 ldg4(const float* p) {
    return __ldg((const float4*)p);
}

__device__ __forceinline__ void red4(float* p, float4 v) {
    asm volatile("red.global.add.v4.f32 [%0], {%1,%2,%3,%4};"
                 :: "l"(p), "f"(v.x), "f"(v.y), "f"(v.z), "f"(v.w) : "memory");
}

__device__ __forceinline__ uint32_t f2tf(float f) {
    uint32_t u;
    asm("cvt.rna.tf32.f32 %0, %1;" : "=r"(u) : "f"(f));
    return u;
}

__device__ __forceinline__ uint32_t packh2(float lo, float hi) {
    __half2 h = __floats2half2_rn(lo, hi);
    return *reinterpret_cast<uint32_t*>(&h);
}

__device__ __forceinline__ void mma8(float* c, const uint32_t* a, const uint32_t* b) {
    asm volatile(
        "mma.sync.aligned.m16n8k8.row.col.f32.tf32.tf32.f32 "
        "{%0,%1,%2,%3}, {%4,%5,%6,%7}, {%8,%9}, {%0,%1,%2,%3};"
        : "+f"(c[0]), "+f"(c[1]), "+f"(c[2]), "+f"(c[3])
        : "r"(a[0]), "r"(a[1]), "r"(a[2]), "r"(a[3]), "r"(b[0]), "r"(b[1]));
}

__device__ __forceinline__ void mma16(float* c, const uint32_t* a, const uint32_t* b) {
    asm volatile(
        "mma.sync.aligned.m16n8k16.row.col.f32.f16.f16.f32 "
        "{%0,%1,%2,%3}, {%4,%5,%6,%7}, {%8,%9}, {%0,%1,%2,%3};"
        : "+f"(c[0]), "+f"(c[1]), "+f"(c[2]), "+f"(c[3])
        : "r"(a[0]), "r"(a[1]), "r"(a[2]), "r"(a[3]), "r"(b[0]), "r"(b[1]));
}

__device__ __forceinline__ void ldA(uint32_t a[4], const uint32_t* As, int stride,
                                    int rowBase, int c0base, int g, int t4) {
    int key = g << 2;
    const uint32_t* p0 = As + (size_t)(rowBase + g) * stride;
    const uint32_t* p1 = p0 + (size_t)8 * stride;
    int c0 = (c0base + t4) ^ key;
    int c1 = (c0base + 4 + t4) ^ key;
    a[0] = p0[c0];
    a[1] = p1[c0];
    a[2] = p0[c1];
    a[3] = p1[c1];
}

__device__ __forceinline__ void ldB4h(uint32_t bf[4][2], const uint32_t* __restrict__ WTp) {
#pragma unroll
    for (int nt = 0; nt < 4; nt++) bf[nt][0] = __ldg(WTp + nt * 8 * 96);
#pragma unroll
    for (int nt = 0; nt < 4; nt++) bf[nt][1] = __ldg(WTp + nt * 8 * 96 + 4);
}

// ---------------------------------------------------------------------------
__global__ void k_prepW(const float* __restrict__ Ws1, const float* __restrict__ Ws2,
                        uint32_t* wt1, uint32_t* wt2) {
    int i = blockIdx.x * blockDim.x + threadIdx.x;
    if (i < 128 * 96) {
        int n = i / 96, kw = i % 96;
        wt1[i] = packh2(__ldg(&Ws1[(size_t)(2 * kw) * 128 + n]),
                        __ldg(&Ws1[(size_t)(2 * kw + 1) * 128 + n]));
        wt2[i] = packh2(__ldg(&Ws2[(size_t)(2 * kw) * 128 + n]),
                        __ldg(&Ws2[(size_t)(2 * kw + 1) * 128 + n]));
    }
}

// ---------------------------------------------------------------------------
__global__ void k_zero(float* cnt, float* s1, float* s2, int n) {
    int i = blockIdx.x * blockDim.x + threadIdx.x;
    int stride = gridDim.x * blockDim.x;
    int t4 = n * 32;
    float4 z = make_float4(0.f, 0.f, 0.f, 0.f);
    for (int j = i; j < t4; j += stride) {
        ((float4*)s1)[j] = z;
        ((float4*)s2)[j] = z;
    }
    for (int j = i; j < n; j += stride) cnt[j] = 0.f;
}

// ---------------------------------------------------------------------------
__global__ void k_agg1(const float* __restrict__ nfeat, const float* __restrict__ efeat,
                       const int* __restrict__ src, const int* __restrict__ dst,
                       float* sum1, float* cnt, int E) {
    int warp = (blockIdx.x * blockDim.x + threadIdx.x) >> 5;
    int lane = threadIdx.x & 31;
    int nw = (gridDim.x * blockDim.x) >> 5;
    for (int e = warp; e < E; e += nw) {
        int s = __ldg(&src[e]);
        int d = __ldg(&dst[e]);
        float4 vs, vd;
        int off;
        if (lane < 16) {
            off = lane * 4;
            vs = ldg4(&nfeat[(size_t)d * 64 + off]);
            vd = ldg4(&nfeat[(size_t)s * 64 + off]);
        } else {
            int q = (lane - 16) * 4;
            off = 64 + q;
            float4 ef = ldg4(&efeat[(size_t)e * 64 + q]);
            vs = ef; vd = ef;
        }
        red4(&sum1[(size_t)s * 128 + off], vs);
        red4(&sum1[(size_t)d * 128 + off], vd);
        if (lane == 0) {
            atomicAdd(&cnt[s], 1.f);
            atomicAdd(&cnt[d], 1.f);
        }
    }
}

// ---------------------------------------------------------------------------
// Tensor-core node projection (tf32) — R12 form (no manual pipelining)
// ---------------------------------------------------------------------------
__global__ __launch_bounds__(128, 4) void k_proj_t(
    const float* __restrict__ sum, const float* __restrict__ cnt,
    const float* __restrict__ W, const float* __restrict__ bias,
    float* __restrict__ proj, int Nn) {
    extern __shared__ uint32_t sm[];
    uint32_t* As = sm;
    __shared__ float invS[32];
    int tid = threadIdx.x, lane = tid & 31, warp = tid >> 5;
    int g = lane >> 2, t4 = lane & 3;
    int n0 = blockIdx.x * 32;
    int ntB = warp * 4;

    if (tid < 32) {
        int n = n0 + tid;
        float c = 1.f;
        if (n < Nn) c = fmaxf(__ldg(&cnt[n]), 1.f);
        invS[tid] = 1.f / c;
    }
    __syncthreads();
    for (int i = tid; i < 32 * 32; i += 128) {
        int r = i >> 5, q = (i & 31) * 4;
        int n = n0 + r;
        float4 v = make_float4(0.f, 0.f, 0.f, 0.f);
        if (n < Nn) v = ldg4(&sum[(size_t)n * 128 + q]);
        float s = invS[r];
        uint4 u;
        u.x = f2tf(v.x * s); u.y = f2tf(v.y * s);
        u.z = f2tf(v.z * s); u.w = f2tf(v.w * s);
        *(uint4*)&As[r * 128 + (q ^ ((r & 7) << 2))] = u;
    }
    __syncthreads();

    float acc[2][4][4];
#pragma unroll
    for (int m = 0; m < 2; m++)
#pragma unroll
        for (int nt = 0; nt < 4; nt++)
#pragma unroll
            for (int k = 0; k < 4; k++) acc[m][nt][k] = 0.f;

    for (int ks = 0; ks < 16; ks++) {
        int k0 = ks * 8;
        uint32_t a[2][4];
        uint32_t bf[4][2];
        const float* Wrow = &W[(size_t)(k0 + t4) * 128 + ntB * 8 + g];
#pragma unroll
        for (int nt = 0; nt < 4; nt++) bf[nt][0] = f2tf(__ldg(&Wrow[nt * 8]));
#pragma unroll
        for (int nt = 0; nt < 4; nt++) bf[nt][1] = f2tf(__ldg(&Wrow[nt * 8 + 4 * 128]));
        ldA(a[0], As, 128, 0, k0, g, t4);
        ldA(a[1], As, 128, 16, k0, g, t4);
#pragma unroll
        for (int nt = 0; nt < 4; nt++) {
            mma8(acc[0][nt], a[0], bf[nt]);
            mma8(acc[1][nt], a[1], bf[nt]);
        }
    }

    __syncthreads();
    float* S = (float*)As;
#pragma unroll
    for (int m = 0; m < 2; m++)
#pragma unroll
        for (int h = 0; h < 2; h++) {
            int r = m * 16 + h * 8 + g;
            int key = (r & 7) << 2;
#pragma unroll
            for (int nt = 0; nt < 4; nt++) {
                int col = (ntB + nt) * 8 + t4 * 2;
                float2 v = make_float2(acc[m][nt][h * 2 + 0], acc[m][nt][h * 2 + 1]);
                *(float2*)&S[r * 128 + (col ^ key)] = v;
            }
        }
    __syncthreads();
    for (int i = tid; i < 32 * 32; i += 128) {
        int r = i >> 5, q = (i & 31) * 4;
        int n = n0 + r;
        if (n < Nn) {
            int key = (r & 7) << 2;
            float4 v = *(float4*)&S[r * 128 + (q ^ key)];
            float4 bb = ldg4(&bias[q]);
            float4 o;
            o.x = v.x + bb.x; o.y = v.y + bb.y; o.z = v.z + bb.z; o.w = v.w + bb.w;
            *(float4*)&proj[(size_t)n * 128 + q] = o;
        }
    }
}

// ---------------------------------------------------------------------------
// fp16 layer-1 edge kernel — two-pass (src then dst), 32-reg accumulators,
// 6 blocks/SM. A tile stays resident; shared GEMM recomputed per pass.
// A words (stride 128): [0,32)=nfeat[src], [32,64)=nfeat[dst],
//                       [64,96)=efeat, [96,128)=te
// WT kw: head [0,32), shared [32,96).
// ---------------------------------------------------------------------------
__global__ __launch_bounds__(128, 6) void k_layer1_t(
    const float* __restrict__ nfeat, const float* __restrict__ efeat,
    const int* __restrict__ src, const int* __restrict__ dst, const float* __restrict__ ts,
    const uint32_t* __restrict__ WT, const float* __restrict__ bias,
    const float* __restrict__ omega, const float* __restrict__ phase,
    const float* __restrict__ proj, __half* __restrict__ outS, __half* __restrict__ outD,
    float* __restrict__ sum2, int E) {
    const int AS = 128;
    extern __shared__ uint32_t sm[];
    uint32_t* A = sm;                       // 32*128 words = 16 KB
    float* Stage = (float*)(sm + 32 * 128); // 32*128 floats = 16 KB
    __shared__ int sI[32], dI[32];
    __shared__ float tsS[32];
    int tid = threadIdx.x, lane = tid & 31, warp = tid >> 5;
    int g = lane >> 2, t4 = lane & 3;
    int e0 = blockIdx.x * 32;
    int ntB = warp * 4;

    if (tid < 32) {
        int e = e0 + tid;
        bool ok = e < E;
        sI[tid] = ok ? __ldg(&src[e]) : 0;
        dI[tid] = ok ? __ldg(&dst[e]) : 0;
        tsS[tid] = ok ? __ldg(&ts[e]) : 0.f;
    }
    __syncthreads();

    for (int i = tid; i < 32 * 48; i += 128) {
        int r = i / 48, p = i % 48;
        int e = e0 + r;
        bool ok = e < E;
        float4 v = make_float4(0.f, 0.f, 0.f, 0.f);
        int col;
        if (p < 16) {
            col = p * 4;
            if (ok) v = ldg4(&nfeat[(size_t)sI[r] * 64 + p * 4]);
        } else if (p < 32) {
            col = 64 + (p - 16) * 4;
            if (ok) v = ldg4(&nfeat[(size_t)dI[r] * 64 + (p - 16) * 4]);
        } else {
            col = 128 + (p - 32) * 4;
            if (ok) v = ldg4(&efeat[(size_t)e * 64 + (p - 32) * 4]);
        }
        uint2 u;
        u.x = packh2(v.x, v.y);
        u.y = packh2(v.z, v.w);
        *(uint2*)&A[r * AS + ((col >> 1) ^ ((r & 7) << 2))] = u;
    }
    for (int i = tid; i < 32 * 16; i += 128) {
        int r = i >> 4, q = (i & 15) * 4;
        float t = tsS[r];
        float c0 = cosf(t * __ldg(&omega[q + 0]) + __ldg(&phase[q + 0]));
        float c1 = cosf(t * __ldg(&omega[q + 1]) + __ldg(&phase[q + 1]));
        float c2 = cosf(t * __ldg(&omega[q + 2]) + __ldg(&phase[q + 2]));
        float c3 = cosf(t * __ldg(&omega[q + 3]) + __ldg(&phase[q + 3]));
        uint2 u;
        u.x = packh2(c0, c1);
        u.y = packh2(c2, c3);
        *(uint2*)&A[r * AS + ((96 + (q >> 1)) ^ ((r & 7) << 2))] = u;
    }
    __syncthreads();

    const uint32_t* WTbase = WT + (size_t)(ntB * 8 + g) * 96 + t4;

#pragma unroll
    for (int pass = 0; pass < 2; pass++) {
        int headA = pass ? 32 : 0;   // src words [0,32), dst words [32,64)
        float acc[2][4][4];
#pragma unroll
        for (int m = 0; m < 2; m++)
#pragma unroll
            for (int nt = 0; nt < 4; nt++)
#pragma unroll
                for (int k = 0; k < 4; k++) acc[m][nt][k] = 0.f;

        // Shared part: A words [64,128), WT kw [32,96)
        for (int ks = 0; ks < 8; ks++) {
            uint32_t a4[2][4];
            uint32_t bf[4][2];
            ldB4h(bf, WTbase + 32 + ks * 8);
            ldA(a4[0], A, AS, 0, 64 + ks * 8, g, t4);
            ldA(a4[1], A, AS, 16, 64 + ks * 8, g, t4);
#pragma unroll
            for (int nt = 0; nt < 4; nt++) {
                mma16(acc[0][nt], a4[0], bf[nt]);
                mma16(acc[1][nt], a4[1], bf[nt]);
            }
        }
        // Head part: WT kw [0,32)
        for (int ks = 0; ks < 4; ks++) {
            uint32_t a4[2][4];
            uint32_t bf[4][2];
            ldB4h(bf, WTbase + ks * 8);
            ldA(a4[0], A, AS, 0, headA + ks * 8, g, t4);
            ldA(a4[1], A, AS, 16, headA + ks * 8, g, t4);
#pragma unroll
            for (int nt = 0; nt < 4; nt++) {
                mma16(acc[0][nt], a4[0], bf[nt]);
                mma16(acc[1][nt], a4[1], bf[nt]);
            }
        }

        // Stage (separate buffer from A); sync orders against previous pass readers
        __syncthreads();
#pragma unroll
        for (int m = 0; m < 2; m++)
#pragma unroll
            for (int h = 0; h < 2; h++) {
                int r = m * 16 + h * 8 + g;
                int key = (r & 7) << 2;
#pragma unroll
                for (int nt = 0; nt < 4; nt++) {
                    int col = (ntB + nt) * 8 + t4 * 2;
                    float2 v = make_float2(acc[m][nt][h * 2 + 0], acc[m][nt][h * 2 + 1]);
                    *(float2*)&Stage[r * 128 + (col ^ key)] = v;
                }
            }
        __syncthreads();

        // Coalesced writeback: pass0 -> outS (+red sum2[dst]); pass1 -> outD (+red sum2[src])
        __half* outP = pass ? outD : outS;
        for (int i = tid; i < 32 * 32; i += 128) {
            int r = i >> 5, q = (i & 31) * 4;
            int e = e0 + r;
            if (e < E) {
                int key = (r & 7) << 2;
                int own = pass ? dI[r] : sI[r];    // node whose proj we add
                int other = pass ? sI[r] : dI[r];  // node receiving the reduction
                float4 v = *(float4*)&Stage[r * 128 + (q ^ key)];
                float4 bb = ldg4(&bias[q]);
                float4 pj = ldg4(&proj[(size_t)own * 128 + q]);
                float4 o;
                o.x = fmaxf(v.x + bb.x + pj.x, 0.f);
                o.y = fmaxf(v.y + bb.y + pj.y, 0.f);
                o.z = fmaxf(v.z + bb.z + pj.z, 0.f);
                o.w = fmaxf(v.w + bb.w + pj.w, 0.f);
                uint2 hp;
                hp.x = packh2(o.x, o.y);
                hp.y = packh2(o.z, o.w);
                *(uint2*)&outP[(size_t)e * 128 + q] = hp;
                red4(&sum2[(size_t)other * 128 + q], o);
            }
        }
    }
}

// ---------------------------------------------------------------------------
// fp16 layer-2 edge kernel — two-pass. A words (stride 160):
// [0,64)=srcF, [64,128)=dstF, [128,160)=te2. WT kw: head [0,64), te [64,96).
// Final f32 output.
// ---------------------------------------------------------------------------
__global__ __launch_bounds__(128, 6) void k_layer2_t(
    const __half* __restrict__ fS, const __half* __restrict__ fD,
    const int* __restrict__ src, const int* __restrict__ dst, const float* __restrict__ ts,
    const uint32_t* __restrict__ WT, const float* __restrict__ bias,
    const float* __restrict__ omega, const float* __restrict__ phase,
    const float* __restrict__ proj, float* __restrict__ outS, float* __restrict__ outD, int E) {
    const int AS = 160;
    extern __shared__ uint32_t sm[];
    uint32_t* A = sm;                        // 32*160 words = 20 KB
    float* Stage = (float*)(sm + 32 * 160);  // 16 KB
    __shared__ int sI[32], dI[32];
    int tid = threadIdx.x, lane = tid & 31, warp = tid >> 5;
    int g = lane >> 2, t4 = lane & 3;
    int e0 = blockIdx.x * 32;
    int ntB = warp * 4;

    if (tid < 32) {
        int e = e0 + tid;
        bool ok = e < E;
        sI[tid] = ok ? __ldg(&src[e]) : 0;
        dI[tid] = ok ? __ldg(&dst[e]) : 0;
    }
    __syncthreads();

    for (int i = tid; i < 32 * 32; i += 128) {
        int r = i >> 5, p = i & 31;
        int e = e0 + r;
        bool ok = e < E;
        uint4 v = make_uint4(0, 0, 0, 0);
        int wcol;
        if (p < 16) {
            wcol = p * 4;
            if (ok) v = *(const uint4*)&fS[(size_t)e * 128 + p * 8];
        } else {
            wcol = 64 + (p - 16) * 4;
            if (ok) v = *(const uint4*)&fD[(size_t)e * 128 + (p - 16) * 8];
        }
        *(uint4*)&A[r * AS + (wcol ^ ((r & 7) << 2))] = v;
    }
    for (int i = tid; i < 32 * 16; i += 128) {
        int r = i >> 4, q = (i & 15) * 4;
        int e = e0 + r;
        float t = (e < E) ? __ldg(&ts[e]) : 0.f;
        float c0 = cosf(t * __ldg(&omega[q + 0]) + __ldg(&phase[q + 0]));
        float c1 = cosf(t * __ldg(&omega[q + 1]) + __ldg(&phase[q + 1]));
        float c2 = cosf(t * __ldg(&omega[q + 2]) + __ldg(&phase[q + 2]));
        float c3 = cosf(t * __ldg(&omega[q + 3]) + __ldg(&phase[q + 3]));
        uint2 u;
        u.x = packh2(c0, c1);
        u.y = packh2(c2, c3);
        *(uint2*)&A[r * AS + ((128 + (q >> 1)) ^ ((r & 7) << 2))] = u;
    }
    __syncthreads();

    const uint32_t* WTbase = WT + (size_t)(ntB * 8 + g) * 96 + t4;

#pragma unroll
    for (int pass = 0; pass < 2; pass++) {
        int headA = pass ? 64 : 0;   // src words [0,64), dst words [64,128)
        float acc[2][4][4];
#pragma unroll
        for (int m = 0; m < 2; m++)
#pragma unroll
            for (int nt = 0; nt < 4; nt++)
#pragma unroll
                for (int k = 0; k < 4; k++) acc[m][nt][k] = 0.f;

        // Shared te part: A words [128,160), WT kw [64,96)
        for (int ks = 0; ks < 4; ks++) {
            uint32_t a4[2][4];
            uint32_t bf[4][2];
            ldB4h(bf, WTbase + 64 + ks * 8);
            ldA(a4[0], A, AS, 0, 128 + ks * 8, g, t4);
            ldA(a4[1], A, AS, 16, 128 + ks * 8, g, t4);
#pragma unroll
            for (int nt = 0; nt < 4; nt++) {
                mma16(acc[0][nt], a4[0], bf[nt]);
                mma16(acc[1][nt], a4[1], bf[nt]);
            }
        }
        // Head: WT kw [0,64)
        for (int ks = 0; ks < 8; ks++) {
            uint32_t a4[2][4];
            uint32_t bf[4][2];
            ldB4h(bf, WTbase + ks * 8);
            ldA(a4[0], A, AS, 0, headA + ks * 8, g, t4);
            ldA(a4[1], A, AS, 16, headA + ks * 8, g, t4);
#pragma unroll
            for (int nt = 0; nt < 4; nt++) {
                mma16(acc[0][nt], a4[0], bf[nt]);
                mma16(acc[1][nt], a4[1], bf[nt]);
            }
        }

        __syncthreads();
#pragma unroll
        for (int m = 0; m < 2; m++)
#pragma unroll
            for (int h = 0; h < 2; h++) {
                int r = m * 16 + h * 8 + g;
                int key = (r & 7) << 2;
#pragma unroll
                for (int nt = 0; nt < 4; nt++) {
                    int col = (ntB + nt) * 8 + t4 * 2;
                    float2 v = make_float2(acc[m][nt][h * 2 + 0], acc[m][nt][h * 2 + 1]);
                    *(float2*)&Stage[r * 128 + (col ^ key)] = v;
                }
            }
        __syncthreads();

        float* outP = pass ? outD : outS;
        for (int i = tid; i < 32 * 32; i += 128) {
            int r = i >> 5, q = (i & 31) * 4;
            int e = e0 + r;
            if (e < E) {
                int key = (r & 7) << 2;
                int own = pass ? dI[r] : sI[r];
                float4 v = *(float4*)&Stage[r * 128 + (q ^ key)];
                float4 bb = ldg4(&bias[q]);
                float4 pj = ldg4(&proj[(size_t)own * 128 + q]);
                float4 o;
                o.x = fmaxf(v.x + bb.x + pj.x, 0.f);
                o.y = fmaxf(v.y + bb.y + pj.y, 0.f);
                o.z = fmaxf(v.z + bb.z + pj.z, 0.f);
                o.w = fmaxf(v.w + bb.w + pj.w, 0.f);
                *(float4*)&outP[(size_t)e * 128 + q] = o;
            }
        }
    }
}

// ---------------------------------------------------------------------------
extern "C" void kernel_launch(void* const* d_in, const int* in_sizes, int n_in,
                              void* d_out, int out_size) {
    const float* nfeat = (const float*)d_in[0];
    const float* efeat = (const float*)d_in[1];
    const int*   src   = (const int*)d_in[2];
    const int*   dst   = (const int*)d_in[3];
    const float* ts    = (const float*)d_in[4];
    const float* Ws1 = (const float*)d_in[5];
    const float* bs1 = (const float*)d_in[6];
    const float* Wn1 = (const float*)d_in[7];
    const float* bn1 = (const float*)d_in[8];
    const float* om1 = (const float*)d_in[9];
    const float* ph1 = (const float*)d_in[10];
    const float* Ws2 = (const float*)d_in[11];
    const float* bs2 = (const float*)d_in[12];
    const float* Wn2 = (const float*)d_in[13];
    const float* bn2 = (const float*)d_in[14];
    const float* om2 = (const float*)d_in[15];
    const float* ph2 = (const float*)d_in[16];

    int Nn = in_sizes[0] / 64;
    int E  = in_sizes[2];

    float *cnt, *s1, *s2, *proj;
    __half *sf, *df;
    uint32_t *wt1, *wt2;
    cudaGetSymbolAddress((void**)&cnt,  g_cnt);
    cudaGetSymbolAddress((void**)&s1,   g_sum1);
    cudaGetSymbolAddress((void**)&s2,   g_sum2);
    cudaGetSymbolAddress((void**)&proj, g_proj);
    cudaGetSymbolAddress((void**)&sf,   g_srcF);
    cudaGetSymbolAddress((void**)&df,   g_dstF);
    cudaGetSymbolAddress((void**)&wt1,  g_WT1);
    cudaGetSymbolAddress((void**)&wt2,  g_WT2);

    float* outv = (float*)d_out;
    int nTileBlocks = (Nn + 31) / 32;
    int eTileBlocks = (E + 31) / 32;

    size_t smProj = (size_t)(32 * 128) * 4;                 // 16 KB
    size_t smL1   = (size_t)(32 * 128 + 32 * 128) * 4;      // 32 KB
    size_t smL2   = (size_t)(32 * 160 + 32 * 128) * 4;      // 36 KB

    cudaFuncSetAttribute(k_proj_t,   cudaFuncAttributeMaxDynamicSharedMemorySize, (int)smProj);
    cudaFuncSetAttribute(k_layer1_t, cudaFuncAttributeMaxDynamicSharedMemorySize, (int)smL1);
    cudaFuncSetAttribute(k_layer2_t, cudaFuncAttributeMaxDynamicSharedMemorySize, (int)smL2);

    k_prepW<<<48, 256>>>(Ws1, Ws2, wt1, wt2);
    k_zero<<<2048, 256>>>(cnt, s1, s2, Nn);
    k_agg1<<<2048, 256>>>(nfeat, efeat, src, dst, s1, cnt, E);
    k_proj_t<<<nTileBlocks, 128, smProj>>>(s1, cnt, Wn1, bn1, proj, Nn);
    k_layer1_t<<<eTileBlocks, 128, smL1>>>(nfeat, efeat, src, dst, ts, wt1, bs1, om1, ph1,
                                           proj, sf, df, s2, E);
    k_proj_t<<<nTileBlocks, 128, smProj>>>(s2, cnt, Wn2, bn2, proj, Nn);
    k_layer2_t<<<eTileBlocks, 128, smL2>>>(sf, df, src, dst, ts, wt2, bs2, om2, ph2,
                                           proj, outv, outv + (size_t)E * 128, E);
}

// round 17
// speedup vs baseline: 1.1007x; 1.1007x over previous
#include <cuda_runtime.h>
#include <cuda_fp16.h>
#include <math.h>
#include <stdint.h>

#define NN 100000
#define EE 500000

__device__ float g_cnt[NN];
__device__ float g_sum1[(size_t)NN * 128];
__device__ float g_sum2[(size_t)NN * 128];
__device__ float g_proj[(size_t)NN * 128];
__device__ __half g_srcF[(size_t)EE * 128];
__device__ __half g_dstF[(size_t)EE * 128];
__device__ uint32_t g_WT1[128 * 96];
__device__ uint32_t g_WT2[128 * 96];

__device__ __forceinline__ float4 ldg4(const float* p) {
    return __ldg((const float4*)p);
}

__device__ __forceinline__ void red4(float* p, float4 v) {
    asm volatile("red.global.add.v4.f32 [%0], {%1,%2,%3,%4};"
                 :: "l"(p), "f"(v.x), "f"(v.y), "f"(v.z), "f"(v.w) : "memory");
}

__device__ __forceinline__ uint32_t f2tf(float f) {
    uint32_t u;
    asm("cvt.rna.tf32.f32 %0, %1;" : "=r"(u) : "f"(f));
    return u;
}

__device__ __forceinline__ uint32_t packh2(float lo, float hi) {
    __half2 h = __floats2half2_rn(lo, hi);
    return *reinterpret_cast<uint32_t*>(&h);
}

__device__ __forceinline__ uint32_t sptr(const void* p) {
    return (uint32_t)__cvta_generic_to_shared(p);
}

__device__ __forceinline__ void mma8(float* c, const uint32_t* a, const uint32_t* b) {
    asm volatile(
        "mma.sync.aligned.m16n8k8.row.col.f32.tf32.tf32.f32 "
        "{%0,%1,%2,%3}, {%4,%5,%6,%7}, {%8,%9}, {%0,%1,%2,%3};"
        : "+f"(c[0]), "+f"(c[1]), "+f"(c[2]), "+f"(c[3])
        : "r"(a[0]), "r"(a[1]), "r"(a[2]), "r"(a[3]), "r"(b[0]), "r"(b[1]));
}

__device__ __forceinline__ void mma16(float* c, const uint32_t* a, const uint32_t* b) {
    asm volatile(
        "mma.sync.aligned.m16n8k16.row.col.f32.f16.f16.f32 "
        "{%0,%1,%2,%3}, {%4,%5,%6,%7}, {%8,%9}, {%0,%1,%2,%3};"
        : "+f"(c[0]), "+f"(c[1]), "+f"(c[2]), "+f"(c[3])
        : "r"(a[0]), "r"(a[1]), "r"(a[2]), "r"(a[3]), "r"(b[0]), "r"(b[1]));
}

// Scalar A-fragment load (tf32 proj kernel)
__device__ __forceinline__ void ldA(uint32_t a[4], const uint32_t* As, int stride,
                                    int rowBase, int c0base, int g, int t4) {
    int key = g << 2;
    const uint32_t* p0 = As + (size_t)(rowBase + g) * stride;
    const uint32_t* p1 = p0 + (size_t)8 * stride;
    int c0 = (c0base + t4) ^ key;
    int c1 = (c0base + 4 + t4) ^ key;
    a[0] = p0[c0];
    a[1] = p1[c0];
    a[2] = p0[c1];
    a[3] = p1[c1];
}

// ldmatrix A-fragment load (fp16 layer kernels): one LDSM.x4 per m16k16 frag.
// Matrix mi = lane/8 (0:r0-7/kLo, 1:r8-15/kLo, 2:r0-7/kHi, 3:r8-15/kHi),
// row rr = lane%7... lane%8. Swizzle key (rr<<2) keeps each 16B row contiguous.
__device__ __forceinline__ void ldmA(uint32_t a[4], uint32_t base, int stride,
                                     int rowBase, int c0base, int lane) {
    int mi = lane >> 3, rr = lane & 7;
    int row = rowBase + ((mi & 1) << 3) + rr;
    int w = (c0base + ((mi >> 1) << 2)) ^ (rr << 2);
    uint32_t addr = base + ((uint32_t)row * stride + w) * 4u;
    asm volatile("ldmatrix.sync.aligned.m8n8.x4.shared.b16 {%0,%1,%2,%3}, [%4];"
                 : "=r"(a[0]), "=r"(a[1]), "=r"(a[2]), "=r"(a[3]) : "r"(addr));
}

__device__ __forceinline__ void ldB4h(uint32_t bf[4][2], const uint32_t* __restrict__ WTp) {
#pragma unroll
    for (int nt = 0; nt < 4; nt++) bf[nt][0] = __ldg(WTp + nt * 8 * 96);
#pragma unroll
    for (int nt = 0; nt < 4; nt++) bf[nt][1] = __ldg(WTp + nt * 8 * 96 + 4);
}

// ---------------------------------------------------------------------------
__global__ void k_prepW(const float* __restrict__ Ws1, const float* __restrict__ Ws2,
                        uint32_t* wt1, uint32_t* wt2) {
    int i = blockIdx.x * blockDim.x + threadIdx.x;
    if (i < 128 * 96) {
        int n = i / 96, kw = i % 96;
        wt1[i] = packh2(__ldg(&Ws1[(size_t)(2 * kw) * 128 + n]),
                        __ldg(&Ws1[(size_t)(2 * kw + 1) * 128 + n]));
        wt2[i] = packh2(__ldg(&Ws2[(size_t)(2 * kw) * 128 + n]),
                        __ldg(&Ws2[(size_t)(2 * kw + 1) * 128 + n]));
    }
}

// ---------------------------------------------------------------------------
__global__ void k_zero(float* cnt, float* s1, float* s2, int n) {
    int i = blockIdx.x * blockDim.x + threadIdx.x;
    int stride = gridDim.x * blockDim.x;
    int t4 = n * 32;
    float4 z = make_float4(0.f, 0.f, 0.f, 0.f);
    for (int j = i; j < t4; j += stride) {
        ((float4*)s1)[j] = z;
        ((float4*)s2)[j] = z;
    }
    for (int j = i; j < n; j += stride) cnt[j] = 0.f;
}

// ---------------------------------------------------------------------------
__global__ void k_agg1(const float* __restrict__ nfeat, const float* __restrict__ efeat,
                       const int* __restrict__ src, const int* __restrict__ dst,
                       float* sum1, float* cnt, int E) {
    int warp = (blockIdx.x * blockDim.x + threadIdx.x) >> 5;
    int lane = threadIdx.x & 31;
    int nw = (gridDim.x * blockDim.x) >> 5;
    for (int e = warp; e < E; e += nw) {
        int s = __ldg(&src[e]);
        int d = __ldg(&dst[e]);
        float4 vs, vd;
        int off;
        if (lane < 16) {
            off = lane * 4;
            vs = ldg4(&nfeat[(size_t)d * 64 + off]);
            vd = ldg4(&nfeat[(size_t)s * 64 + off]);
        } else {
            int q = (lane - 16) * 4;
            off = 64 + q;
            float4 ef = ldg4(&efeat[(size_t)e * 64 + q]);
            vs = ef; vd = ef;
        }
        red4(&sum1[(size_t)s * 128 + off], vs);
        red4(&sum1[(size_t)d * 128 + off], vd);
        if (lane == 0) {
            atomicAdd(&cnt[s], 1.f);
            atomicAdd(&cnt[d], 1.f);
        }
    }
}

// ---------------------------------------------------------------------------
// Tensor-core node projection (tf32) — unchanged from R12
// ---------------------------------------------------------------------------
__global__ __launch_bounds__(128, 4) void k_proj_t(
    const float* __restrict__ sum, const float* __restrict__ cnt,
    const float* __restrict__ W, const float* __restrict__ bias,
    float* __restrict__ proj, int Nn) {
    extern __shared__ uint32_t sm[];
    uint32_t* As = sm;
    __shared__ float invS[32];
    int tid = threadIdx.x, lane = tid & 31, warp = tid >> 5;
    int g = lane >> 2, t4 = lane & 3;
    int n0 = blockIdx.x * 32;
    int ntB = warp * 4;

    if (tid < 32) {
        int n = n0 + tid;
        float c = 1.f;
        if (n < Nn) c = fmaxf(__ldg(&cnt[n]), 1.f);
        invS[tid] = 1.f / c;
    }
    __syncthreads();
    for (int i = tid; i < 32 * 32; i += 128) {
        int r = i >> 5, q = (i & 31) * 4;
        int n = n0 + r;
        float4 v = make_float4(0.f, 0.f, 0.f, 0.f);
        if (n < Nn) v = ldg4(&sum[(size_t)n * 128 + q]);
        float s = invS[r];
        uint4 u;
        u.x = f2tf(v.x * s); u.y = f2tf(v.y * s);
        u.z = f2tf(v.z * s); u.w = f2tf(v.w * s);
        *(uint4*)&As[r * 128 + (q ^ ((r & 7) << 2))] = u;
    }
    __syncthreads();

    float acc[2][4][4];
#pragma unroll
    for (int m = 0; m < 2; m++)
#pragma unroll
        for (int nt = 0; nt < 4; nt++)
#pragma unroll
            for (int k = 0; k < 4; k++) acc[m][nt][k] = 0.f;

    for (int ks = 0; ks < 16; ks++) {
        int k0 = ks * 8;
        uint32_t a[2][4];
        uint32_t bf[4][2];
        const float* Wrow = &W[(size_t)(k0 + t4) * 128 + ntB * 8 + g];
#pragma unroll
        for (int nt = 0; nt < 4; nt++) bf[nt][0] = f2tf(__ldg(&Wrow[nt * 8]));
#pragma unroll
        for (int nt = 0; nt < 4; nt++) bf[nt][1] = f2tf(__ldg(&Wrow[nt * 8 + 4 * 128]));
        ldA(a[0], As, 128, 0, k0, g, t4);
        ldA(a[1], As, 128, 16, k0, g, t4);
#pragma unroll
        for (int nt = 0; nt < 4; nt++) {
            mma8(acc[0][nt], a[0], bf[nt]);
            mma8(acc[1][nt], a[1], bf[nt]);
        }
    }

    __syncthreads();
    float* S = (float*)As;
#pragma unroll
    for (int m = 0; m < 2; m++)
#pragma unroll
        for (int h = 0; h < 2; h++) {
            int r = m * 16 + h * 8 + g;
            int key = (r & 7) << 2;
#pragma unroll
            for (int nt = 0; nt < 4; nt++) {
                int col = (ntB + nt) * 8 + t4 * 2;
                float2 v = make_float2(acc[m][nt][h * 2 + 0], acc[m][nt][h * 2 + 1]);
                *(float2*)&S[r * 128 + (col ^ key)] = v;
            }
        }
    __syncthreads();
    for (int i = tid; i < 32 * 32; i += 128) {
        int r = i >> 5, q = (i & 31) * 4;
        int n = n0 + r;
        if (n < Nn) {
            int key = (r & 7) << 2;
            float4 v = *(float4*)&S[r * 128 + (q ^ key)];
            float4 bb = ldg4(&bias[q]);
            float4 o;
            o.x = v.x + bb.x; o.y = v.y + bb.y; o.z = v.z + bb.z; o.w = v.w + bb.w;
            *(float4*)&proj[(size_t)n * 128 + q] = o;
        }
    }
}

// ---------------------------------------------------------------------------
// fp16 layer-1 edge kernel (R12 structure, ldmatrix A loads).
// A words (stride 128): [0,32)=nfeat[src], [32,64)=nfeat[dst],
//                       [64,96)=efeat, [96,128)=te
// WT kw: head [0,32), shared [32,96).
// ---------------------------------------------------------------------------
__global__ __launch_bounds__(128, 4) void k_layer1_t(
    const float* __restrict__ nfeat, const float* __restrict__ efeat,
    const int* __restrict__ src, const int* __restrict__ dst, const float* __restrict__ ts,
    const uint32_t* __restrict__ WT, const float* __restrict__ bias,
    const float* __restrict__ omega, const float* __restrict__ phase,
    const float* __restrict__ proj, __half* __restrict__ outS, __half* __restrict__ outD,
    float* __restrict__ sum2, int E) {
    const int AS = 128;
    extern __shared__ uint32_t sm[];
    uint32_t* A = sm;
    __shared__ int sI[32], dI[32];
    __shared__ float tsS[32];
    int tid = threadIdx.x, lane = tid & 31, warp = tid >> 5;
    int g = lane >> 2, t4 = lane & 3;
    int e0 = blockIdx.x * 32;
    int ntB = warp * 4;
    uint32_t Ab = sptr(A);

    if (tid < 32) {
        int e = e0 + tid;
        bool ok = e < E;
        sI[tid] = ok ? __ldg(&src[e]) : 0;
        dI[tid] = ok ? __ldg(&dst[e]) : 0;
        tsS[tid] = ok ? __ldg(&ts[e]) : 0.f;
    }
    __syncthreads();

    for (int i = tid; i < 32 * 48; i += 128) {
        int r = i / 48, p = i % 48;
        int e = e0 + r;
        bool ok = e < E;
        float4 v = make_float4(0.f, 0.f, 0.f, 0.f);
        int col;
        if (p < 16) {
            col = p * 4;
            if (ok) v = ldg4(&nfeat[(size_t)sI[r] * 64 + p * 4]);
        } else if (p < 32) {
            col = 64 + (p - 16) * 4;
            if (ok) v = ldg4(&nfeat[(size_t)dI[r] * 64 + (p - 16) * 4]);
        } else {
            col = 128 + (p - 32) * 4;
            if (ok) v = ldg4(&efeat[(size_t)e * 64 + (p - 32) * 4]);
        }
        uint2 u;
        u.x = packh2(v.x, v.y);
        u.y = packh2(v.z, v.w);
        *(uint2*)&A[r * AS + ((col >> 1) ^ ((r & 7) << 2))] = u;
    }
    for (int i = tid; i < 32 * 16; i += 128) {
        int r = i >> 4, q = (i & 15) * 4;
        float t = tsS[r];
        float c0 = cosf(t * __ldg(&omega[q + 0]) + __ldg(&phase[q + 0]));
        float c1 = cosf(t * __ldg(&omega[q + 1]) + __ldg(&phase[q + 1]));
        float c2 = cosf(t * __ldg(&omega[q + 2]) + __ldg(&phase[q + 2]));
        float c3 = cosf(t * __ldg(&omega[q + 3]) + __ldg(&phase[q + 3]));
        uint2 u;
        u.x = packh2(c0, c1);
        u.y = packh2(c2, c3);
        *(uint2*)&A[r * AS + ((96 + (q >> 1)) ^ ((r & 7) << 2))] = u;
    }
    __syncthreads();

    float acc1[2][4][4], acc2[2][4][4];
#pragma unroll
    for (int m = 0; m < 2; m++)
#pragma unroll
        for (int nt = 0; nt < 4; nt++)
#pragma unroll
            for (int k = 0; k < 4; k++) acc1[m][nt][k] = 0.f;

    const uint32_t* WTbase = WT + (size_t)(ntB * 8 + g) * 96 + t4;

    // Shared part: A words [64,128), WT kw [32,96)
    for (int ks = 0; ks < 8; ks++) {
        uint32_t a4[2][4];
        uint32_t bf[4][2];
        ldB4h(bf, WTbase + 32 + ks * 8);
        ldmA(a4[0], Ab, AS, 0, 64 + ks * 8, lane);
        ldmA(a4[1], Ab, AS, 16, 64 + ks * 8, lane);
#pragma unroll
        for (int nt = 0; nt < 4; nt++) {
            mma16(acc1[0][nt], a4[0], bf[nt]);
            mma16(acc1[1][nt], a4[1], bf[nt]);
        }
    }
#pragma unroll
    for (int m = 0; m < 2; m++)
#pragma unroll
        for (int nt = 0; nt < 4; nt++)
#pragma unroll
            for (int k = 0; k < 4; k++) acc2[m][nt][k] = acc1[m][nt][k];

    // Head: WT kw [0,32); src words [0,32) -> acc1, dst words [32,64) -> acc2
    for (int ks = 0; ks < 4; ks++) {
        uint32_t aS4[2][4], aD4[2][4];
        uint32_t bf[4][2];
        ldB4h(bf, WTbase + ks * 8);
        ldmA(aS4[0], Ab, AS, 0, ks * 8, lane);
        ldmA(aS4[1], Ab, AS, 16, ks * 8, lane);
        ldmA(aD4[0], Ab, AS, 0, 32 + ks * 8, lane);
        ldmA(aD4[1], Ab, AS, 16, 32 + ks * 8, lane);
#pragma unroll
        for (int nt = 0; nt < 4; nt++) {
            mma16(acc1[0][nt], aS4[0], bf[nt]);
            mma16(acc1[1][nt], aS4[1], bf[nt]);
            mma16(acc2[0][nt], aD4[0], bf[nt]);
            mma16(acc2[1][nt], aD4[1], bf[nt]);
        }
    }

    __syncthreads();
    float* Ss = (float*)sm;
    float* Sd = (float*)sm + 32 * 128;
#pragma unroll
    for (int m = 0; m < 2; m++)
#pragma unroll
        for (int h = 0; h < 2; h++) {
            int r = m * 16 + h * 8 + g;
            int key = (r & 7) << 2;
#pragma unroll
            for (int nt = 0; nt < 4; nt++) {
                int col = (ntB + nt) * 8 + t4 * 2;
                float2 vs = make_float2(acc1[m][nt][h * 2 + 0], acc1[m][nt][h * 2 + 1]);
                float2 vd = make_float2(acc2[m][nt][h * 2 + 0], acc2[m][nt][h * 2 + 1]);
                *(float2*)&Ss[r * 128 + (col ^ key)] = vs;
                *(float2*)&Sd[r * 128 + (col ^ key)] = vd;
            }
        }
    __syncthreads();
    for (int i = tid; i < 32 * 32; i += 128) {
        int r = i >> 5, q = (i & 31) * 4;
        int e = e0 + r;
        if (e < E) {
            int key = (r & 7) << 2;
            int s = sI[r], d = dI[r];
            float4 vs = *(float4*)&Ss[r * 128 + (q ^ key)];
            float4 vd = *(float4*)&Sd[r * 128 + (q ^ key)];
            float4 bb = ldg4(&bias[q]);
            float4 ps = ldg4(&proj[(size_t)s * 128 + q]);
            float4 pd = ldg4(&proj[(size_t)d * 128 + q]);
            float4 os, od;
            os.x = fmaxf(vs.x + bb.x + ps.x, 0.f);
            os.y = fmaxf(vs.y + bb.y + ps.y, 0.f);
            os.z = fmaxf(vs.z + bb.z + ps.z, 0.f);
            os.w = fmaxf(vs.w + bb.w + ps.w, 0.f);
            od.x = fmaxf(vd.x + bb.x + pd.x, 0.f);
            od.y = fmaxf(vd.y + bb.y + pd.y, 0.f);
            od.z = fmaxf(vd.z + bb.z + pd.z, 0.f);
            od.w = fmaxf(vd.w + bb.w + pd.w, 0.f);
            uint2 hs, hd;
            hs.x = packh2(os.x, os.y); hs.y = packh2(os.z, os.w);
            hd.x = packh2(od.x, od.y); hd.y = packh2(od.z, od.w);
            *(uint2*)&outS[(size_t)e * 128 + q] = hs;
            *(uint2*)&outD[(size_t)e * 128 + q] = hd;
            red4(&sum2[(size_t)s * 128 + q], od);
            red4(&sum2[(size_t)d * 128 + q], os);
        }
    }
}

// ---------------------------------------------------------------------------
// fp16 layer-2 edge kernel (R12 structure, ldmatrix A loads).
// A words (stride 160): [0,64)=srcF, [64,128)=dstF, [128,160)=te2
// WT kw: head [0,64), te [64,96). Writes final f32 output.
// ---------------------------------------------------------------------------
__global__ __launch_bounds__(128, 4) void k_layer2_t(
    const __half* __restrict__ fS, const __half* __restrict__ fD,
    const int* __restrict__ src, const int* __restrict__ dst, const float* __restrict__ ts,
    const uint32_t* __restrict__ WT, const float* __restrict__ bias,
    const float* __restrict__ omega, const float* __restrict__ phase,
    const float* __restrict__ proj, float* __restrict__ outS, float* __restrict__ outD, int E) {
    const int AS = 160;
    extern __shared__ uint32_t sm[];
    uint32_t* A = sm;
    __shared__ int sI[32], dI[32];
    int tid = threadIdx.x, lane = tid & 31, warp = tid >> 5;
    int g = lane >> 2, t4 = lane & 3;
    int e0 = blockIdx.x * 32;
    int ntB = warp * 4;
    uint32_t Ab = sptr(A);

    if (tid < 32) {
        int e = e0 + tid;
        bool ok = e < E;
        sI[tid] = ok ? __ldg(&src[e]) : 0;
        dI[tid] = ok ? __ldg(&dst[e]) : 0;
    }
    __syncthreads();

    for (int i = tid; i < 32 * 32; i += 128) {
        int r = i >> 5, p = i & 31;
        int e = e0 + r;
        bool ok = e < E;
        uint4 v = make_uint4(0, 0, 0, 0);
        int wcol;
        if (p < 16) {
            wcol = p * 4;
            if (ok) v = *(const uint4*)&fS[(size_t)e * 128 + p * 8];
        } else {
            wcol = 64 + (p - 16) * 4;
            if (ok) v = *(const uint4*)&fD[(size_t)e * 128 + (p - 16) * 8];
        }
        *(uint4*)&A[r * AS + (wcol ^ ((r & 7) << 2))] = v;
    }
    for (int i = tid; i < 32 * 16; i += 128) {
        int r = i >> 4, q = (i & 15) * 4;
        int e = e0 + r;
        float t = (e < E) ? __ldg(&ts[e]) : 0.f;
        float c0 = cosf(t * __ldg(&omega[q + 0]) + __ldg(&phase[q + 0]));
        float c1 = cosf(t * __ldg(&omega[q + 1]) + __ldg(&phase[q + 1]));
        float c2 = cosf(t * __ldg(&omega[q + 2]) + __ldg(&phase[q + 2]));
        float c3 = cosf(t * __ldg(&omega[q + 3]) + __ldg(&phase[q + 3]));
        uint2 u;
        u.x = packh2(c0, c1);
        u.y = packh2(c2, c3);
        *(uint2*)&A[r * AS + ((128 + (q >> 1)) ^ ((r & 7) << 2))] = u;
    }
    __syncthreads();

    float acc1[2][4][4], acc2[2][4][4];
#pragma unroll
    for (int m = 0; m < 2; m++)
#pragma unroll
        for (int nt = 0; nt < 4; nt++)
#pragma unroll
            for (int k = 0; k < 4; k++) acc1[m][nt][k] = 0.f;

    const uint32_t* WTbase = WT + (size_t)(ntB * 8 + g) * 96 + t4;

    // Shared te part: A words [128,160), WT kw [64,96)
    for (int ks = 0; ks < 4; ks++) {
        uint32_t a4[2][4];
        uint32_t bf[4][2];
        ldB4h(bf, WTbase + 64 + ks * 8);
        ldmA(a4[0], Ab, AS, 0, 128 + ks * 8, lane);
        ldmA(a4[1], Ab, AS, 16, 128 + ks * 8, lane);
#pragma unroll
        for (int nt = 0; nt < 4; nt++) {
            mma16(acc1[0][nt], a4[0], bf[nt]);
            mma16(acc1[1][nt], a4[1], bf[nt]);
        }
    }
#pragma unroll
    for (int m = 0; m < 2; m++)
#pragma unroll
        for (int nt = 0; nt < 4; nt++)
#pragma unroll
            for (int k = 0; k < 4; k++) acc2[m][nt][k] = acc1[m][nt][k];

    // Head: WT kw [0,64); src words [0,64) -> acc1, dst words [64,128) -> acc2
    for (int ks = 0; ks < 8; ks++) {
        uint32_t aS4[2][4], aD4[2][4];
        uint32_t bf[4][2];
        ldB4h(bf, WTbase + ks * 8);
        ldmA(aS4[0], Ab, AS, 0, ks * 8, lane);
        ldmA(aS4[1], Ab, AS, 16, ks * 8, lane);
        ldmA(aD4[0], Ab, AS, 0, 64 + ks * 8, lane);
        ldmA(aD4[1], Ab, AS, 16, 64 + ks * 8, lane);
#pragma unroll
        for (int nt = 0; nt < 4; nt++) {
            mma16(acc1[0][nt], aS4[0], bf[nt]);
            mma16(acc1[1][nt], aS4[1], bf[nt]);
            mma16(acc2[0][nt], aD4[0], bf[nt]);
            mma16(acc2[1][nt], aD4[1], bf[nt]);
        }
    }

    __syncthreads();
    float* Ss = (float*)sm;
    float* Sd = (float*)sm + 32 * 128;
#pragma unroll
    for (int m = 0; m < 2; m++)
#pragma unroll
        for (int h = 0; h < 2; h++) {
            int r = m * 16 + h * 8 + g;
            int key = (r & 7) << 2;
#pragma unroll
            for (int nt = 0; nt < 4; nt++) {
                int col = (ntB + nt) * 8 + t4 * 2;
                float2 vs = make_float2(acc1[m][nt][h * 2 + 0], acc1[m][nt][h * 2 + 1]);
                float2 vd = make_float2(acc2[m][nt][h * 2 + 0], acc2[m][nt][h * 2 + 1]);
                *(float2*)&Ss[r * 128 + (col ^ key)] = vs;
                *(float2*)&Sd[r * 128 + (col ^ key)] = vd;
            }
        }
    __syncthreads();
    for (int i = tid; i < 32 * 32; i += 128) {
        int r = i >> 5, q = (i & 31) * 4;
        int e = e0 + r;
        if (e < E) {
            int key = (r & 7) << 2;
            int s = sI[r], d = dI[r];
            float4 vs = *(float4*)&Ss[r * 128 + (q ^ key)];
            float4 vd = *(float4*)&Sd[r * 128 + (q ^ key)];
            float4 bb = ldg4(&bias[q]);
            float4 ps = ldg4(&proj[(size_t)s * 128 + q]);
            float4 pd = ldg4(&proj[(size_t)d * 128 + q]);
            float4 os, od;
            os.x = fmaxf(vs.x + bb.x + ps.x, 0.f);
            os.y = fmaxf(vs.y + bb.y + ps.y, 0.f);
            os.z = fmaxf(vs.z + bb.z + ps.z, 0.f);
            os.w = fmaxf(vs.w + bb.w + ps.w, 0.f);
            od.x = fmaxf(vd.x + bb.x + pd.x, 0.f);
            od.y = fmaxf(vd.y + bb.y + pd.y, 0.f);
            od.z = fmaxf(vd.z + bb.z + pd.z, 0.f);
            od.w = fmaxf(vd.w + bb.w + pd.w, 0.f);
            *(float4*)&outS[(size_t)e * 128 + q] = os;
            *(float4*)&outD[(size_t)e * 128 + q] = od;
        }
    }
}

// ---------------------------------------------------------------------------
extern "C" void kernel_launch(void* const* d_in, const int* in_sizes, int n_in,
                              void* d_out, int out_size) {
    const float* nfeat = (const float*)d_in[0];
    const float* efeat = (const float*)d_in[1];
    const int*   src   = (const int*)d_in[2];
    const int*   dst   = (const int*)d_in[3];
    const float* ts    = (const float*)d_in[4];
    const float* Ws1 = (const float*)d_in[5];
    const float* bs1 = (const float*)d_in[6];
    const float* Wn1 = (const float*)d_in[7];
    const float* bn1 = (const float*)d_in[8];
    const float* om1 = (const float*)d_in[9];
    const float* ph1 = (const float*)d_in[10];
    const float* Ws2 = (const float*)d_in[11];
    const float* bs2 = (const float*)d_in[12];
    const float* Wn2 = (const float*)d_in[13];
    const float* bn2 = (const float*)d_in[14];
    const float* om2 = (const float*)d_in[15];
    const float* ph2 = (const float*)d_in[16];

    int Nn = in_sizes[0] / 64;
    int E  = in_sizes[2];

    float *cnt, *s1, *s2, *proj;
    __half *sf, *df;
    uint32_t *wt1, *wt2;
    cudaGetSymbolAddress((void**)&cnt,  g_cnt);
    cudaGetSymbolAddress((void**)&s1,   g_sum1);
    cudaGetSymbolAddress((void**)&s2,   g_sum2);
    cudaGetSymbolAddress((void**)&proj, g_proj);
    cudaGetSymbolAddress((void**)&sf,   g_srcF);
    cudaGetSymbolAddress((void**)&df,   g_dstF);
    cudaGetSymbolAddress((void**)&wt1,  g_WT1);
    cudaGetSymbolAddress((void**)&wt2,  g_WT2);

    float* outv = (float*)d_out;
    int nTileBlocks = (Nn + 31) / 32;
    int eTileBlocks = (E + 31) / 32;

    size_t smProj = (size_t)(32 * 128) * 4;   // 16 KB
    size_t smL    = (size_t)(64 * 128) * 4;   // 32 KB

    cudaFuncSetAttribute(k_proj_t,   cudaFuncAttributeMaxDynamicSharedMemorySize, (int)smProj);
    cudaFuncSetAttribute(k_layer1_t, cudaFuncAttributeMaxDynamicSharedMemorySize, (int)smL);
    cudaFuncSetAttribute(k_layer2_t, cudaFuncAttributeMaxDynamicSharedMemorySize, (int)smL);

    k_prepW<<<48, 256>>>(Ws1, Ws2, wt1, wt2);
    k_zero<<<2048, 256>>>(cnt, s1, s2, Nn);
    k_agg1<<<2048, 256>>>(nfeat, efeat, src, dst, s1, cnt, E);
    k_proj_t<<<nTileBlocks, 128, smProj>>>(s1, cnt, Wn1, bn1, proj, Nn);
    k_layer1_t<<<eTileBlocks, 128, smL>>>(nfeat, efeat, src, dst, ts, wt1, bs1, om1, ph1,
                                          proj, sf, df, s2, E);
    k_proj_t<<<nTileBlocks, 128, smProj>>>(s2, cnt, Wn2, bn2, proj, Nn);
    k_layer2_t<<<eTileBlocks, 128, smL>>>(sf, df, src, dst, ts, wt2, bs2, om2, ph2,
                                          proj, outv, outv + (size_t)E * 128, E);
}